// round 6
// baseline (speedup 1.0000x reference)
#include <cuda_runtime.h>
#include <cuda_bf16.h>
#include <cstdint>

// ---------------------------------------------------------------------------
// ACCGraphSAGE: h0 = relu(feat@W0); 3x { agg = mean_in(h); h = relu(agg@Ws[l]) }
// out = concat([h0..h3], dim=1) -> [N, 512] fp32
// R6: batched (4-edge/thread) CSR atomics for MLP; CSR chain overlapped with
//     conv+gemm0 on a forked capture stream; agg unrolled 8-wide.
// ---------------------------------------------------------------------------

#define MAX_N 50000
#define MAX_E 800000
#define HID 128
#define NTILES ((MAX_N + 63) / 64)     // 782

__device__ int g_counts[MAX_N];
__device__ int g_rowstart[MAX_N + 1];
__device__ int g_csr_src[MAX_E];
__device__ __align__(16) unsigned char g_xh[NTILES * 16384];
__device__ __align__(16) unsigned char g_xl[NTILES * 16384];
__device__ __align__(16) unsigned char g_wh[4 * 32768];
__device__ __align__(16) unsigned char g_wl[4 * 32768];

// ---------------------------------------------------------------------------
// helpers
// ---------------------------------------------------------------------------
__device__ __forceinline__ uint32_t s2u(const void* p) {
    uint32_t a;
    asm("{ .reg .u64 t; cvta.to.shared.u64 t, %1; cvt.u32.u64 %0, t; }"
        : "=r"(a) : "l"(p));
    return a;
}

__device__ __forceinline__ uint32_t swz(uint32_t row, uint32_t kelem) {
    return row * 256u + ((((kelem >> 3) ^ (row & 7u)) & 15u) << 4) +
           ((kelem & 7u) << 1);
}

__device__ __forceinline__ void ldsm_x4(uint32_t* d, uint32_t addr) {
    asm volatile("ldmatrix.sync.aligned.m8n8.x4.shared.b16 {%0,%1,%2,%3}, [%4];"
                 : "=r"(d[0]), "=r"(d[1]), "=r"(d[2]), "=r"(d[3]) : "r"(addr));
}
__device__ __forceinline__ void ldsm_x2t(uint32_t* d, uint32_t addr) {
    asm volatile("ldmatrix.sync.aligned.m8n8.x2.trans.shared.b16 {%0,%1}, [%2];"
                 : "=r"(d[0]), "=r"(d[1]) : "r"(addr));
}
__device__ __forceinline__ void mma_bf16(float* c, const uint32_t* a,
                                         const uint32_t* b) {
    asm volatile(
        "mma.sync.aligned.m16n8k16.row.col.f32.bf16.bf16.f32 "
        "{%0,%1,%2,%3}, {%4,%5,%6,%7}, {%8,%9}, {%0,%1,%2,%3};"
        : "+f"(c[0]), "+f"(c[1]), "+f"(c[2]), "+f"(c[3])
        : "r"(a[0]), "r"(a[1]), "r"(a[2]), "r"(a[3]), "r"(b[0]), "r"(b[1]));
}

__device__ __forceinline__ void store_hilo(unsigned char* xh, unsigned char* xl,
                                           size_t tileBase, uint32_t r, uint32_t k,
                                           float4 v) {
    __nv_bfloat162 h01 = __floats2bfloat162_rn(v.x, v.y);
    __nv_bfloat162 h23 = __floats2bfloat162_rn(v.z, v.w);
    __nv_bfloat162 l01 = __floats2bfloat162_rn(v.x - __bfloat162float(h01.x),
                                               v.y - __bfloat162float(h01.y));
    __nv_bfloat162 l23 = __floats2bfloat162_rn(v.z - __bfloat162float(h23.x),
                                               v.w - __bfloat162float(h23.y));
    uint32_t o0 = swz(r, k), o1 = swz(r, k + 2);
    *reinterpret_cast<__nv_bfloat162*>(xh + tileBase + o0) = h01;
    *reinterpret_cast<__nv_bfloat162*>(xh + tileBase + o1) = h23;
    *reinterpret_cast<__nv_bfloat162*>(xl + tileBase + o0) = l01;
    *reinterpret_cast<__nv_bfloat162*>(xl + tileBase + o1) = l23;
}

// ---------------------------------------------------------------------------
// CSR build (counting sort by dst) — 4 edges/thread for atomic MLP
// ---------------------------------------------------------------------------
__global__ void count_kernel(const int* __restrict__ dst, int* __restrict__ counts, int E) {
    int i = (blockIdx.x * blockDim.x + threadIdx.x) * 4;
    if (i + 4 <= E) {
        int4 d = *reinterpret_cast<const int4*>(dst + i);
        atomicAdd(&counts[d.x], 1);
        atomicAdd(&counts[d.y], 1);
        atomicAdd(&counts[d.z], 1);
        atomicAdd(&counts[d.w], 1);
    } else {
        for (; i < E; i++) atomicAdd(&counts[dst[i]], 1);
    }
}

__global__ void scan_kernel(int* __restrict__ counts, int* __restrict__ rowstart, int N) {
    __shared__ int part[1024];
    int tid = threadIdx.x;
    int chunk = (N + 1023) >> 10;
    int s = tid * chunk;
    int e = s + chunk; if (e > N) e = N; if (s > N) s = N;
    int sum = 0;
    for (int i = s; i < e; i++) sum += counts[i];
    part[tid] = sum;
    __syncthreads();
    for (int off = 1; off < 1024; off <<= 1) {
        int v = (tid >= off) ? part[tid - off] : 0;
        __syncthreads();
        part[tid] += v;
        __syncthreads();
    }
    int run = (tid == 0) ? 0 : part[tid - 1];
    for (int i = s; i < e; i++) {
        int c = counts[i];
        rowstart[i] = run;
        counts[i] = run;
        run += c;
    }
    if (tid == 1023) rowstart[N] = run;
}

__global__ void scatter_kernel(const int* __restrict__ src, const int* __restrict__ dst,
                               int* __restrict__ cursor, int* __restrict__ csr, int E) {
    int i = (blockIdx.x * blockDim.x + threadIdx.x) * 4;
    if (i + 4 <= E) {
        int4 d = *reinterpret_cast<const int4*>(dst + i);
        int4 s = *reinterpret_cast<const int4*>(src + i);
        int p0 = atomicAdd(&cursor[d.x], 1);
        int p1 = atomicAdd(&cursor[d.y], 1);
        int p2 = atomicAdd(&cursor[d.z], 1);
        int p3 = atomicAdd(&cursor[d.w], 1);
        csr[p0] = s.x; csr[p1] = s.y; csr[p2] = s.z; csr[p3] = s.w;
    } else {
        for (; i < E; i++) {
            int pos = atomicAdd(&cursor[dst[i]], 1);
            csr[pos] = src[i];
        }
    }
}

// ---------------------------------------------------------------------------
// combined converter: weights (all layers) + feat -> swizzled hi/lo bf16 tiles
// idx space: [0, (L+1)*4096) = weights, [(L+1)*4096, +N*32) = feat
// ---------------------------------------------------------------------------
__global__ void conv_kernel(const float* __restrict__ feat,
                            const float* __restrict__ W0,
                            const float* __restrict__ Ws,
                            unsigned char* __restrict__ xh,
                            unsigned char* __restrict__ xl,
                            unsigned char* __restrict__ wh,
                            unsigned char* __restrict__ wl, int L, int N) {
    int idx = blockIdx.x * blockDim.x + threadIdx.x;
    int wtot = (L + 1) * 4096;
    if (idx < wtot) {
        int layer = idx >> 12;
        int rem = idx & 4095;
        int k = rem >> 5;
        int n = (rem & 31) * 4;
        const float* w = (layer == 0) ? W0 : (Ws + (size_t)(layer - 1) * HID * HID);
        float4 v = *reinterpret_cast<const float4*>(w + (size_t)k * HID + n);
        store_hilo(wh, wl, (size_t)layer * 32768, (uint32_t)k, (uint32_t)n, v);
    } else {
        int t = idx - wtot;
        if (t >= N * 32) return;
        int r = t >> 5;
        int k = (t & 31) * 4;
        float4 v = *reinterpret_cast<const float4*>(feat + (size_t)r * HID + k);
        store_hilo(xh, xl, (size_t)(r >> 6) * 16384, (uint32_t)(r & 63),
                   (uint32_t)k, v);
    }
}

// ---------------------------------------------------------------------------
// Mean aggregation: one warp per dst node, 8-wide MLP; emits hi/lo bf16 tiles
// ---------------------------------------------------------------------------
__global__ void agg_kernel(const float4* __restrict__ h4, int rs4,
                           const int* __restrict__ rowstart,
                           const int* __restrict__ csr,
                           unsigned char* __restrict__ xh,
                           unsigned char* __restrict__ xl, int N) {
    int node = (blockIdx.x * blockDim.x + threadIdx.x) >> 5;
    int lane = threadIdx.x & 31;
    if (node >= N) return;
    int s = rowstart[node];
    int e = rowstart[node + 1];
    float4 acc = make_float4(0.f, 0.f, 0.f, 0.f);
    int i = s;
    for (; i + 8 <= e; i += 8) {
        int sv[8];
        #pragma unroll
        for (int q = 0; q < 8; q++) sv[q] = csr[i + q];
        float4 v[8];
        #pragma unroll
        for (int q = 0; q < 8; q++) v[q] = h4[(size_t)sv[q] * rs4 + lane];
        float4 p0, p1;
        p0.x = v[0].x + v[1].x; p0.y = v[0].y + v[1].y;
        p0.z = v[0].z + v[1].z; p0.w = v[0].w + v[1].w;
        p1.x = v[2].x + v[3].x; p1.y = v[2].y + v[3].y;
        p1.z = v[2].z + v[3].z; p1.w = v[2].w + v[3].w;
        p0.x += v[4].x + v[5].x; p0.y += v[4].y + v[5].y;
        p0.z += v[4].z + v[5].z; p0.w += v[4].w + v[5].w;
        p1.x += v[6].x + v[7].x; p1.y += v[6].y + v[7].y;
        p1.z += v[6].z + v[7].z; p1.w += v[6].w + v[7].w;
        acc.x += p0.x + p1.x; acc.y += p0.y + p1.y;
        acc.z += p0.z + p1.z; acc.w += p0.w + p1.w;
    }
    for (; i < e; i++) {
        int sv = csr[i];
        float4 v = h4[(size_t)sv * rs4 + lane];
        acc.x += v.x; acc.y += v.y; acc.z += v.z; acc.w += v.w;
    }
    float inv = (e > s) ? (1.f / (float)(e - s)) : 0.f;
    acc.x *= inv; acc.y *= inv; acc.z *= inv; acc.w *= inv;
    store_hilo(xh, xl, (size_t)(node >> 6) * 16384, (uint32_t)(node & 63),
               (uint32_t)(lane * 4), acc);
}

// ---------------------------------------------------------------------------
// mma.sync GEMM + ReLU over pre-swizzled bf16 tiles (as R5)
// ---------------------------------------------------------------------------
#define GT 256
#define S_XH 0
#define S_XL 16384
#define S_BH 32768
#define S_BL 65536
#define GEMM_SMEM 98304

__global__ void __launch_bounds__(GT, 2)
gemm_mma_kernel(const unsigned char* __restrict__ xh,
                const unsigned char* __restrict__ xl,
                const unsigned char* __restrict__ wh,
                const unsigned char* __restrict__ wl,
                float* __restrict__ outBlk, int N, int outStride) {
    extern __shared__ char smem[];
    uint32_t sb = s2u(smem);
    int tid = threadIdx.x;
    int lane = tid & 31;
    int w = tid >> 5;
    int row0 = blockIdx.x * 64;

    {
        const uint4* gx = reinterpret_cast<const uint4*>(xh + (size_t)blockIdx.x * 16384);
        const uint4* gl = reinterpret_cast<const uint4*>(xl + (size_t)blockIdx.x * 16384);
        uint4* sx = reinterpret_cast<uint4*>(smem + S_XH);
        uint4* sl = reinterpret_cast<uint4*>(smem + S_XL);
        #pragma unroll
        for (int i = 0; i < 4; i++) {
            sx[tid + i * GT] = gx[tid + i * GT];
            sl[tid + i * GT] = gl[tid + i * GT];
        }
        const uint4* gbh = reinterpret_cast<const uint4*>(wh);
        const uint4* gbl = reinterpret_cast<const uint4*>(wl);
        uint4* sbh = reinterpret_cast<uint4*>(smem + S_BH);
        uint4* sbl = reinterpret_cast<uint4*>(smem + S_BL);
        #pragma unroll
        for (int i = 0; i < 8; i++) {
            sbh[tid + i * GT] = gbh[tid + i * GT];
            sbl[tid + i * GT] = gbl[tid + i * GT];
        }
    }
    __syncthreads();

    const int rw = (w & 1) * 32;
    const int cw = (w >> 1) * 32;

    float acc[2][4][4];
    #pragma unroll
    for (int i = 0; i < 2; i++)
        #pragma unroll
        for (int j = 0; j < 4; j++)
            #pragma unroll
            for (int q = 0; q < 4; q++) acc[i][j][q] = 0.f;

    const int l2 = lane & 15;
    #pragma unroll
    for (int pass = 0; pass < 3; pass++) {
        const uint32_t aBase = sb + (pass == 2 ? S_XL : S_XH);
        const uint32_t bBase = sb + (pass == 1 ? S_BL : S_BH);
        #pragma unroll
        for (int kc = 0; kc < 8; kc++) {
            uint32_t a[2][4];
            #pragma unroll
            for (int i = 0; i < 2; i++) {
                uint32_t ar = (uint32_t)(rw + i * 16 + (lane & 15));
                uint32_t ak = (uint32_t)(kc * 16 + (lane >> 4) * 8);
                ldsm_x4(a[i], aBase + swz(ar, ak));
            }
            #pragma unroll
            for (int j = 0; j < 4; j++) {
                uint32_t b[2];
                uint32_t bk = (uint32_t)(kc * 16 + (l2 & 7) + ((l2 >> 3) & 1) * 8);
                uint32_t bn = (uint32_t)(cw + j * 8);
                ldsm_x2t(b, bBase + swz(bk, bn));
                mma_bf16(acc[0][j], a[0], b);
                mma_bf16(acc[1][j], a[1], b);
            }
        }
    }

    #pragma unroll
    for (int i = 0; i < 2; i++) {
        int rA = row0 + rw + i * 16 + (lane >> 2);
        int rB = rA + 8;
        #pragma unroll
        for (int j = 0; j < 4; j++) {
            int c = cw + j * 8 + (lane & 3) * 2;
            if (rA < N) {
                float2 v = make_float2(fmaxf(acc[i][j][0], 0.f),
                                       fmaxf(acc[i][j][1], 0.f));
                *reinterpret_cast<float2*>(outBlk + (size_t)rA * outStride + c) = v;
            }
            if (rB < N) {
                float2 v = make_float2(fmaxf(acc[i][j][2], 0.f),
                                       fmaxf(acc[i][j][3], 0.f));
                *reinterpret_cast<float2*>(outBlk + (size_t)rB * outStride + c) = v;
            }
        }
    }
}

// ---------------------------------------------------------------------------
// launch: CSR chain on main stream, conv+gemm0 forked onto a second stream
// ---------------------------------------------------------------------------
extern "C" void kernel_launch(void* const* d_in, const int* in_sizes, int n_in,
                              void* d_out, int out_size) {
    const float* feat = (const float*)d_in[0];
    const int*   src  = (const int*)d_in[1];
    const int*   dst  = (const int*)d_in[2];
    const float* W0   = (const float*)d_in[3];
    const float* Ws   = (const float*)d_in[4];
    float* out = (float*)d_out;

    int N = in_sizes[0] / HID;
    int E = in_sizes[1];
    int L = in_sizes[4] / (HID * HID);
    int outStride = (L + 1) * HID;

    int* counts;    cudaGetSymbolAddress((void**)&counts, g_counts);
    int* rowstart;  cudaGetSymbolAddress((void**)&rowstart, g_rowstart);
    int* csr;       cudaGetSymbolAddress((void**)&csr, g_csr_src);
    unsigned char *xh, *xl, *wh, *wl;
    cudaGetSymbolAddress((void**)&xh, g_xh);
    cudaGetSymbolAddress((void**)&xl, g_xl);
    cudaGetSymbolAddress((void**)&wh, g_wh);
    cudaGetSymbolAddress((void**)&wl, g_wl);

    cudaFuncSetAttribute(gemm_mma_kernel, cudaFuncAttributeMaxDynamicSharedMemorySize,
                         GEMM_SMEM);

    int gemm_grid = (N + 63) / 64;
    int eThreads4 = (E + 3) / 4;

    // fork a side stream for conv + gemm0 (independent of CSR build)
    cudaStream_t s2;
    cudaStreamCreateWithFlags(&s2, cudaStreamNonBlocking);
    cudaEvent_t evF, evJ;
    cudaEventCreateWithFlags(&evF, cudaEventDisableTiming);
    cudaEventCreateWithFlags(&evJ, cudaEventDisableTiming);

    cudaEventRecord(evF, 0);
    cudaStreamWaitEvent(s2, evF, 0);

    // side stream: convert weights+feat, then layer-0 GEMM -> out[:,0:128]
    int convTot = (L + 1) * 4096 + N * 32;
    conv_kernel<<<(convTot + 255) / 256, 256, 0, s2>>>(feat, W0, Ws, xh, xl, wh, wl, L, N);
    gemm_mma_kernel<<<gemm_grid, GT, GEMM_SMEM, s2>>>(xh, xl, wh, wl, out, N, outStride);

    // main stream: CSR build
    cudaMemsetAsync(counts, 0, (size_t)N * sizeof(int), 0);
    count_kernel<<<(eThreads4 + 255) / 256, 256>>>(dst, counts, E);
    scan_kernel<<<1, 1024>>>(counts, rowstart, N);
    scatter_kernel<<<(eThreads4 + 255) / 256, 256>>>(src, dst, counts, csr, E);

    // join
    cudaEventRecord(evJ, s2);
    cudaStreamWaitEvent(0, evJ, 0);

    int agg_grid = (N + 7) / 8;
    for (int l = 0; l < L; l++) {
        agg_kernel<<<agg_grid, 256>>>(
            reinterpret_cast<const float4*>(out + (size_t)l * HID), outStride / 4,
            rowstart, csr, xh, xl, N);
        gemm_mma_kernel<<<gemm_grid, GT, GEMM_SMEM>>>(
            xh, xl, wh + (size_t)(l + 1) * 32768, wl + (size_t)(l + 1) * 32768,
            out + (size_t)(l + 1) * HID, N, outStride);
    }

    cudaEventDestroy(evF);
    cudaEventDestroy(evJ);
    cudaStreamDestroy(s2);
    (void)n_in; (void)out_size;
}

// round 7
// speedup vs baseline: 1.4238x; 1.4238x over previous
#include <cuda_runtime.h>
#include <cuda_bf16.h>
#include <cstdint>

// ---------------------------------------------------------------------------
// ACCGraphSAGE: h0 = relu(feat@W0); 3x { agg = mean_in(h); h = relu(agg@Ws[l]) }
// out = concat([h0..h3], dim=1) -> [N, 512] fp32
// R7: multi-block CSR scan (was 72us single-block!), no stream fork,
//     4-wide CSR atomics, merged conv, 8-wide agg, R5 mma GEMM.
// ---------------------------------------------------------------------------

#define MAX_N 50000
#define MAX_E 800000
#define HID 128
#define NTILES ((MAX_N + 63) / 64)     // 782
#define SCAN_BLKS ((MAX_N + 255) / 256)  // 196

__device__ int g_counts[MAX_N];
__device__ int g_rowstart[MAX_N + 1];
__device__ int g_csr_src[MAX_E];
__device__ int g_blocksums[SCAN_BLKS];
__device__ int g_blockoff[SCAN_BLKS];
__device__ __align__(16) unsigned char g_xh[NTILES * 16384];
__device__ __align__(16) unsigned char g_xl[NTILES * 16384];
__device__ __align__(16) unsigned char g_wh[4 * 32768];
__device__ __align__(16) unsigned char g_wl[4 * 32768];

// ---------------------------------------------------------------------------
// helpers
// ---------------------------------------------------------------------------
__device__ __forceinline__ uint32_t s2u(const void* p) {
    uint32_t a;
    asm("{ .reg .u64 t; cvta.to.shared.u64 t, %1; cvt.u32.u64 %0, t; }"
        : "=r"(a) : "l"(p));
    return a;
}

__device__ __forceinline__ uint32_t swz(uint32_t row, uint32_t kelem) {
    return row * 256u + ((((kelem >> 3) ^ (row & 7u)) & 15u) << 4) +
           ((kelem & 7u) << 1);
}

__device__ __forceinline__ void ldsm_x4(uint32_t* d, uint32_t addr) {
    asm volatile("ldmatrix.sync.aligned.m8n8.x4.shared.b16 {%0,%1,%2,%3}, [%4];"
                 : "=r"(d[0]), "=r"(d[1]), "=r"(d[2]), "=r"(d[3]) : "r"(addr));
}
__device__ __forceinline__ void ldsm_x2t(uint32_t* d, uint32_t addr) {
    asm volatile("ldmatrix.sync.aligned.m8n8.x2.trans.shared.b16 {%0,%1}, [%2];"
                 : "=r"(d[0]), "=r"(d[1]) : "r"(addr));
}
__device__ __forceinline__ void mma_bf16(float* c, const uint32_t* a,
                                         const uint32_t* b) {
    asm volatile(
        "mma.sync.aligned.m16n8k16.row.col.f32.bf16.bf16.f32 "
        "{%0,%1,%2,%3}, {%4,%5,%6,%7}, {%8,%9}, {%0,%1,%2,%3};"
        : "+f"(c[0]), "+f"(c[1]), "+f"(c[2]), "+f"(c[3])
        : "r"(a[0]), "r"(a[1]), "r"(a[2]), "r"(a[3]), "r"(b[0]), "r"(b[1]));
}

__device__ __forceinline__ void store_hilo(unsigned char* xh, unsigned char* xl,
                                           size_t tileBase, uint32_t r, uint32_t k,
                                           float4 v) {
    __nv_bfloat162 h01 = __floats2bfloat162_rn(v.x, v.y);
    __nv_bfloat162 h23 = __floats2bfloat162_rn(v.z, v.w);
    __nv_bfloat162 l01 = __floats2bfloat162_rn(v.x - __bfloat162float(h01.x),
                                               v.y - __bfloat162float(h01.y));
    __nv_bfloat162 l23 = __floats2bfloat162_rn(v.z - __bfloat162float(h23.x),
                                               v.w - __bfloat162float(h23.y));
    uint32_t o0 = swz(r, k), o1 = swz(r, k + 2);
    *reinterpret_cast<__nv_bfloat162*>(xh + tileBase + o0) = h01;
    *reinterpret_cast<__nv_bfloat162*>(xh + tileBase + o1) = h23;
    *reinterpret_cast<__nv_bfloat162*>(xl + tileBase + o0) = l01;
    *reinterpret_cast<__nv_bfloat162*>(xl + tileBase + o1) = l23;
}

// ---------------------------------------------------------------------------
// CSR build — 4 edges/thread atomics, multi-block scan
// ---------------------------------------------------------------------------
__global__ void count_kernel(const int* __restrict__ dst, int* __restrict__ counts, int E) {
    int i = (blockIdx.x * blockDim.x + threadIdx.x) * 4;
    if (i + 4 <= E) {
        int4 d = *reinterpret_cast<const int4*>(dst + i);
        atomicAdd(&counts[d.x], 1);
        atomicAdd(&counts[d.y], 1);
        atomicAdd(&counts[d.z], 1);
        atomicAdd(&counts[d.w], 1);
    } else {
        for (; i < E; i++) atomicAdd(&counts[dst[i]], 1);
    }
}

// phase 1: per-block exclusive scan; partial results into rowstart,
// block totals into blocksums
__global__ void scan1_kernel(const int* __restrict__ counts,
                             int* __restrict__ rowstart,
                             int* __restrict__ blocksums, int N) {
    __shared__ int sh[256];
    int tid = threadIdx.x;
    int i = blockIdx.x * 256 + tid;
    int c = (i < N) ? counts[i] : 0;
    sh[tid] = c;
    __syncthreads();
    #pragma unroll
    for (int off = 1; off < 256; off <<= 1) {
        int v = (tid >= off) ? sh[tid - off] : 0;
        __syncthreads();
        sh[tid] += v;
        __syncthreads();
    }
    if (i < N) rowstart[i] = sh[tid] - c;   // exclusive, block-local
    if (tid == 255) blocksums[blockIdx.x] = sh[255];
}

// phase 2: single block scans the block sums (exclusive)
__global__ void scan2_kernel(const int* __restrict__ blocksums,
                             int* __restrict__ blockoff, int nb) {
    __shared__ int sh[256];
    int tid = threadIdx.x;
    int c = (tid < nb) ? blocksums[tid] : 0;
    sh[tid] = c;
    __syncthreads();
    #pragma unroll
    for (int off = 1; off < 256; off <<= 1) {
        int v = (tid >= off) ? sh[tid - off] : 0;
        __syncthreads();
        sh[tid] += v;
        __syncthreads();
    }
    if (tid < nb) blockoff[tid] = sh[tid] - c;
}

// phase 3: add block offsets; counts becomes scatter cursor
__global__ void scan3_kernel(int* __restrict__ rowstart,
                             int* __restrict__ counts,
                             const int* __restrict__ blockoff, int N, int E) {
    int i = blockIdx.x * 256 + threadIdx.x;
    if (i < N) {
        int v = rowstart[i] + blockoff[blockIdx.x];
        rowstart[i] = v;
        counts[i] = v;
    }
    if (i == 0) rowstart[N] = E;
}

__global__ void scatter_kernel(const int* __restrict__ src, const int* __restrict__ dst,
                               int* __restrict__ cursor, int* __restrict__ csr, int E) {
    int i = (blockIdx.x * blockDim.x + threadIdx.x) * 4;
    if (i + 4 <= E) {
        int4 d = *reinterpret_cast<const int4*>(dst + i);
        int4 s = *reinterpret_cast<const int4*>(src + i);
        int p0 = atomicAdd(&cursor[d.x], 1);
        int p1 = atomicAdd(&cursor[d.y], 1);
        int p2 = atomicAdd(&cursor[d.z], 1);
        int p3 = atomicAdd(&cursor[d.w], 1);
        csr[p0] = s.x; csr[p1] = s.y; csr[p2] = s.z; csr[p3] = s.w;
    } else {
        for (; i < E; i++) {
            int pos = atomicAdd(&cursor[dst[i]], 1);
            csr[pos] = src[i];
        }
    }
}

// ---------------------------------------------------------------------------
// combined converter: weights (all layers) + feat -> swizzled hi/lo bf16 tiles
// ---------------------------------------------------------------------------
__global__ void conv_kernel(const float* __restrict__ feat,
                            const float* __restrict__ W0,
                            const float* __restrict__ Ws,
                            unsigned char* __restrict__ xh,
                            unsigned char* __restrict__ xl,
                            unsigned char* __restrict__ wh,
                            unsigned char* __restrict__ wl, int L, int N) {
    int idx = blockIdx.x * blockDim.x + threadIdx.x;
    int wtot = (L + 1) * 4096;
    if (idx < wtot) {
        int layer = idx >> 12;
        int rem = idx & 4095;
        int k = rem >> 5;
        int n = (rem & 31) * 4;
        const float* w = (layer == 0) ? W0 : (Ws + (size_t)(layer - 1) * HID * HID);
        float4 v = *reinterpret_cast<const float4*>(w + (size_t)k * HID + n);
        store_hilo(wh, wl, (size_t)layer * 32768, (uint32_t)k, (uint32_t)n, v);
    } else {
        int t = idx - wtot;
        if (t >= N * 32) return;
        int r = t >> 5;
        int k = (t & 31) * 4;
        float4 v = *reinterpret_cast<const float4*>(feat + (size_t)r * HID + k);
        store_hilo(xh, xl, (size_t)(r >> 6) * 16384, (uint32_t)(r & 63),
                   (uint32_t)k, v);
    }
}

// ---------------------------------------------------------------------------
// Mean aggregation: one warp per dst node, 8-wide MLP; emits hi/lo bf16 tiles
// ---------------------------------------------------------------------------
__global__ void agg_kernel(const float4* __restrict__ h4, int rs4,
                           const int* __restrict__ rowstart,
                           const int* __restrict__ csr,
                           unsigned char* __restrict__ xh,
                           unsigned char* __restrict__ xl, int N) {
    int node = (blockIdx.x * blockDim.x + threadIdx.x) >> 5;
    int lane = threadIdx.x & 31;
    if (node >= N) return;
    int s = rowstart[node];
    int e = rowstart[node + 1];
    float4 acc = make_float4(0.f, 0.f, 0.f, 0.f);
    int i = s;
    for (; i + 8 <= e; i += 8) {
        int sv[8];
        #pragma unroll
        for (int q = 0; q < 8; q++) sv[q] = csr[i + q];
        float4 v[8];
        #pragma unroll
        for (int q = 0; q < 8; q++) v[q] = h4[(size_t)sv[q] * rs4 + lane];
        float4 p0, p1;
        p0.x = v[0].x + v[1].x; p0.y = v[0].y + v[1].y;
        p0.z = v[0].z + v[1].z; p0.w = v[0].w + v[1].w;
        p1.x = v[2].x + v[3].x; p1.y = v[2].y + v[3].y;
        p1.z = v[2].z + v[3].z; p1.w = v[2].w + v[3].w;
        p0.x += v[4].x + v[5].x; p0.y += v[4].y + v[5].y;
        p0.z += v[4].z + v[5].z; p0.w += v[4].w + v[5].w;
        p1.x += v[6].x + v[7].x; p1.y += v[6].y + v[7].y;
        p1.z += v[6].z + v[7].z; p1.w += v[6].w + v[7].w;
        acc.x += p0.x + p1.x; acc.y += p0.y + p1.y;
        acc.z += p0.z + p1.z; acc.w += p0.w + p1.w;
    }
    for (; i < e; i++) {
        int sv = csr[i];
        float4 v = h4[(size_t)sv * rs4 + lane];
        acc.x += v.x; acc.y += v.y; acc.z += v.z; acc.w += v.w;
    }
    float inv = (e > s) ? (1.f / (float)(e - s)) : 0.f;
    acc.x *= inv; acc.y *= inv; acc.z *= inv; acc.w *= inv;
    store_hilo(xh, xl, (size_t)(node >> 6) * 16384, (uint32_t)(node & 63),
               (uint32_t)(lane * 4), acc);
}

// ---------------------------------------------------------------------------
// mma.sync GEMM + ReLU over pre-swizzled bf16 tiles
// ---------------------------------------------------------------------------
#define GT 256
#define S_XH 0
#define S_XL 16384
#define S_BH 32768
#define S_BL 65536
#define GEMM_SMEM 98304

__global__ void __launch_bounds__(GT, 2)
gemm_mma_kernel(const unsigned char* __restrict__ xh,
                const unsigned char* __restrict__ xl,
                const unsigned char* __restrict__ wh,
                const unsigned char* __restrict__ wl,
                float* __restrict__ outBlk, int N, int outStride) {
    extern __shared__ char smem[];
    uint32_t sb = s2u(smem);
    int tid = threadIdx.x;
    int lane = tid & 31;
    int w = tid >> 5;
    int row0 = blockIdx.x * 64;

    {
        const uint4* gx = reinterpret_cast<const uint4*>(xh + (size_t)blockIdx.x * 16384);
        const uint4* gl = reinterpret_cast<const uint4*>(xl + (size_t)blockIdx.x * 16384);
        uint4* sx = reinterpret_cast<uint4*>(smem + S_XH);
        uint4* sl = reinterpret_cast<uint4*>(smem + S_XL);
        #pragma unroll
        for (int i = 0; i < 4; i++) {
            sx[tid + i * GT] = gx[tid + i * GT];
            sl[tid + i * GT] = gl[tid + i * GT];
        }
        const uint4* gbh = reinterpret_cast<const uint4*>(wh);
        const uint4* gbl = reinterpret_cast<const uint4*>(wl);
        uint4* sbh = reinterpret_cast<uint4*>(smem + S_BH);
        uint4* sbl = reinterpret_cast<uint4*>(smem + S_BL);
        #pragma unroll
        for (int i = 0; i < 8; i++) {
            sbh[tid + i * GT] = gbh[tid + i * GT];
            sbl[tid + i * GT] = gbl[tid + i * GT];
        }
    }
    __syncthreads();

    const int rw = (w & 1) * 32;
    const int cw = (w >> 1) * 32;

    float acc[2][4][4];
    #pragma unroll
    for (int i = 0; i < 2; i++)
        #pragma unroll
        for (int j = 0; j < 4; j++)
            #pragma unroll
            for (int q = 0; q < 4; q++) acc[i][j][q] = 0.f;

    const int l2 = lane & 15;
    #pragma unroll
    for (int pass = 0; pass < 3; pass++) {
        const uint32_t aBase = sb + (pass == 2 ? S_XL : S_XH);
        const uint32_t bBase = sb + (pass == 1 ? S_BL : S_BH);
        #pragma unroll
        for (int kc = 0; kc < 8; kc++) {
            uint32_t a[2][4];
            #pragma unroll
            for (int i = 0; i < 2; i++) {
                uint32_t ar = (uint32_t)(rw + i * 16 + (lane & 15));
                uint32_t ak = (uint32_t)(kc * 16 + (lane >> 4) * 8);
                ldsm_x4(a[i], aBase + swz(ar, ak));
            }
            #pragma unroll
            for (int j = 0; j < 4; j++) {
                uint32_t b[2];
                uint32_t bk = (uint32_t)(kc * 16 + (l2 & 7) + ((l2 >> 3) & 1) * 8);
                uint32_t bn = (uint32_t)(cw + j * 8);
                ldsm_x2t(b, bBase + swz(bk, bn));
                mma_bf16(acc[0][j], a[0], b);
                mma_bf16(acc[1][j], a[1], b);
            }
        }
    }

    #pragma unroll
    for (int i = 0; i < 2; i++) {
        int rA = row0 + rw + i * 16 + (lane >> 2);
        int rB = rA + 8;
        #pragma unroll
        for (int j = 0; j < 4; j++) {
            int c = cw + j * 8 + (lane & 3) * 2;
            if (rA < N) {
                float2 v = make_float2(fmaxf(acc[i][j][0], 0.f),
                                       fmaxf(acc[i][j][1], 0.f));
                *reinterpret_cast<float2*>(outBlk + (size_t)rA * outStride + c) = v;
            }
            if (rB < N) {
                float2 v = make_float2(fmaxf(acc[i][j][2], 0.f),
                                       fmaxf(acc[i][j][3], 0.f));
                *reinterpret_cast<float2*>(outBlk + (size_t)rB * outStride + c) = v;
            }
        }
    }
}

// ---------------------------------------------------------------------------
// launch: single stream, serial
// ---------------------------------------------------------------------------
extern "C" void kernel_launch(void* const* d_in, const int* in_sizes, int n_in,
                              void* d_out, int out_size) {
    const float* feat = (const float*)d_in[0];
    const int*   src  = (const int*)d_in[1];
    const int*   dst  = (const int*)d_in[2];
    const float* W0   = (const float*)d_in[3];
    const float* Ws   = (const float*)d_in[4];
    float* out = (float*)d_out;

    int N = in_sizes[0] / HID;
    int E = in_sizes[1];
    int L = in_sizes[4] / (HID * HID);
    int outStride = (L + 1) * HID;

    int* counts;    cudaGetSymbolAddress((void**)&counts, g_counts);
    int* rowstart;  cudaGetSymbolAddress((void**)&rowstart, g_rowstart);
    int* csr;       cudaGetSymbolAddress((void**)&csr, g_csr_src);
    int* bsums;     cudaGetSymbolAddress((void**)&bsums, g_blocksums);
    int* boff;      cudaGetSymbolAddress((void**)&boff, g_blockoff);
    unsigned char *xh, *xl, *wh, *wl;
    cudaGetSymbolAddress((void**)&xh, g_xh);
    cudaGetSymbolAddress((void**)&xl, g_xl);
    cudaGetSymbolAddress((void**)&wh, g_wh);
    cudaGetSymbolAddress((void**)&wl, g_wl);

    cudaFuncSetAttribute(gemm_mma_kernel, cudaFuncAttributeMaxDynamicSharedMemorySize,
                         GEMM_SMEM);

    int gemm_grid = (N + 63) / 64;
    int eThreads4 = (E + 3) / 4;
    int scanBlks = (N + 255) / 256;

    // CSR build
    cudaMemsetAsync(counts, 0, (size_t)N * sizeof(int), 0);
    count_kernel<<<(eThreads4 + 255) / 256, 256>>>(dst, counts, E);
    scan1_kernel<<<scanBlks, 256>>>(counts, rowstart, bsums, N);
    scan2_kernel<<<1, 256>>>(bsums, boff, scanBlks);
    scan3_kernel<<<scanBlks, 256>>>(rowstart, counts, boff, N, E);
    scatter_kernel<<<(eThreads4 + 255) / 256, 256>>>(src, dst, counts, csr, E);

    // convert weights + feat, then layer-0 GEMM
    int convTot = (L + 1) * 4096 + N * 32;
    conv_kernel<<<(convTot + 255) / 256, 256>>>(feat, W0, Ws, xh, xl, wh, wl, L, N);
    gemm_mma_kernel<<<gemm_grid, GT, GEMM_SMEM>>>(xh, xl, wh, wl, out, N, outStride);

    int agg_grid = (N + 7) / 8;
    for (int l = 0; l < L; l++) {
        agg_kernel<<<agg_grid, 256>>>(
            reinterpret_cast<const float4*>(out + (size_t)l * HID), outStride / 4,
            rowstart, csr, xh, xl, N);
        gemm_mma_kernel<<<gemm_grid, GT, GEMM_SMEM>>>(
            xh, xl, wh + (size_t)(l + 1) * 32768, wl + (size_t)(l + 1) * 32768,
            out + (size_t)(l + 1) * HID, N, outStride);
    }
    (void)n_in; (void)out_size;
}